// round 15
// baseline (speedup 1.0000x reference)
#include <cuda_runtime.h>
#include <cuda_fp16.h>
#include <math.h>
#include <float.h>

#define NOFF 20
#define HDIM 128
#define SEQN 8192
#define NH   16
#define NB   2
#define WARPS 8
#define QPW   8                        // queries per warp -> 64 queries/block
#define TOTE (NB * NH * SEQN * HDIM)   // 33554432 elements per tensor

// interleaved fp16 mirror: per row n, 32 blocks of 8 halfs {k[4i..4i+4), v[4i..4i+4)}
__device__ __half g_kv[2 * TOTE];

__device__ __forceinline__ unsigned int h2u(__half2 h) {
    union { __half2 h; unsigned int u; } c; c.h = h; return c.u;
}
__device__ __forceinline__ unsigned long long f2add(unsigned long long a, unsigned long long b) {
    unsigned long long d;
    asm("add.rn.f32x2 %0, %1, %2;" : "=l"(d) : "l"(a), "l"(b));
    return d;
}
__device__ __forceinline__ unsigned long long f2pack(float lo, float hi) {
    unsigned long long d;
    asm("mov.b64 %0, {%1, %2};" : "=l"(d) : "f"(lo), "f"(hi));
    return d;
}
__device__ __forceinline__ float2 f2unpack(unsigned long long a) {
    float lo, hi;
    asm("mov.b64 {%0, %1}, %2;" : "=f"(lo), "=f"(hi) : "l"(a));
    return make_float2(lo, hi);
}
// packed butterfly: reduces both packed floats across the full warp, result in all lanes
__device__ __forceinline__ float2 wredux2(float a, float b) {
    unsigned long long u = f2pack(a, b);
#pragma unroll
    for (int o = 16; o; o >>= 1) u = f2add(u, __shfl_xor_sync(0xffffffffu, u, o));
    return f2unpack(u);
}

// ---- pre-pass: fp32 k,v -> interleaved fp16 mirror (streaming) ----
__global__ void __launch_bounds__(256) cvt_kv(const float* __restrict__ k, const float* __restrict__ v)
{
    const int total4 = TOTE / 4;
    for (int i = blockIdx.x * blockDim.x + threadIdx.x; i < total4; i += gridDim.x * blockDim.x) {
        float4 a = __ldcs(((const float4*)k) + i);
        float4 b = __ldcs(((const float4*)v) + i);
        uint4 o;
        o.x = h2u(__floats2half2_rn(a.x, a.y));
        o.y = h2u(__floats2half2_rn(a.z, a.w));
        o.z = h2u(__floats2half2_rn(b.x, b.y));
        o.w = h2u(__floats2half2_rn(b.z, b.w));
        ((uint4*)g_kv)[i] = o;   // block index == source float4 index -> coalesced
    }
}

__global__ void __launch_bounds__(256, 4) dsqg_fwd(
    const float* __restrict__ q, const float* __restrict__ pb,
    const float* __restrict__ se, float* __restrict__ out)
{
    constexpr int offs[NOFF] = {1,2,3,4,5,6,7,8,9,11,13,15,16,23,32,64,128,256,512,1024};

    __shared__ __align__(16) __half2 se_h[NOFF * HDIM / 2];   // fp16 scale_embed (5KB)
    __shared__ float pb_s[NOFF];

    const int tid = threadIdx.x;
    const int w   = tid >> 5;
    const int l   = tid & 31;

    const int bid = blockIdx.x;
    const int bh  = bid >> 7;
    const int n0  = (bid & 127) * 64;
    const int h   = bh & (NH - 1);

    for (int i = tid; i < NOFF * HDIM / 2; i += 256) {
        float2 f = ((const float2*)se)[i];
        se_h[i] = __float22half2_rn(f);
    }
    if (tid < NOFF) pb_s[tid] = pb[tid * NH + h];
    __syncthreads();

    const float sc = 0.088388347648318447f;      // 1/sqrt(128)
    const size_t base = (size_t)bh * SEQN * HDIM;
    const __half* kvb = g_kv + 2 * base;         // 256 halfs per row

    for (int it = 0; it < QPW; ++it) {
        const int n = n0 + it * WARPS + w;       // warp owns query n

        // q slice (4 dims), prescaled by 1/sqrt(hd)
        const float4 qv = *(const float4*)(q + base + (size_t)n * HDIM + l * 4);
        const float q0 = qv.x * sc, q1 = qv.y * sc, q2 = qv.z * sc, q3 = qv.w * sc;

        float o0 = 0.f, o1 = 0.f, o2 = 0.f, o3 = 0.f, lsum = 0.f;

#pragma unroll
        for (int t = 0; t < NOFF / 2; ++t) {
            const int ja = 2 * t, jb = 2 * t + 1;
            int kpa = n - offs[ja]; if (kpa < 0) kpa = 0;
            int kpb = n - offs[jb]; if (kpb < 0) kpb = 0;
            // one LDG.128 per offset fetches this lane's k AND v slices
            const uint4 kva = *(const uint4*)(kvb + (size_t)kpa * 256 + l * 8);
            const uint4 kvb2 = *(const uint4*)(kvb + (size_t)kpb * 256 + l * 8);
            const uint2 sha = *(const uint2*)(se_h + ja * (HDIM / 2) + 2 * l);
            const uint2 shb = *(const uint2*)(se_h + jb * (HDIM / 2) + 2 * l);

            const float2 a01 = __half22float2(__hadd2(*(const __half2*)&kva.x, *(const __half2*)&sha.x));
            const float2 a23 = __half22float2(__hadd2(*(const __half2*)&kva.y, *(const __half2*)&sha.y));
            const float2 b01 = __half22float2(__hadd2(*(const __half2*)&kvb2.x, *(const __half2*)&shb.x));
            const float2 b23 = __half22float2(__hadd2(*(const __half2*)&kvb2.y, *(const __half2*)&shb.y));

            const float accA = fmaf(q0, a01.x, fmaf(q1, a01.y, fmaf(q2, a23.x, q3 * a23.y)));
            const float accB = fmaf(q0, b01.x, fmaf(q1, b01.y, fmaf(q2, b23.x, q3 * b23.y)));

            // one packed butterfly reduces both offsets' scores into all lanes
            const float2 s = wredux2(accA, accB);
            const float eA = (n >= offs[ja]) ? __expf(s.x + pb_s[ja]) : 0.f;
            const float eB = (n >= offs[jb]) ? __expf(s.y + pb_s[jb]) : 0.f;
            lsum += eA + eB;

            const float2 vA01 = __half22float2(*(const __half2*)&kva.z);
            const float2 vA23 = __half22float2(*(const __half2*)&kva.w);
            const float2 vB01 = __half22float2(*(const __half2*)&kvb2.z);
            const float2 vB23 = __half22float2(*(const __half2*)&kvb2.w);
            o0 = fmaf(eA, vA01.x, fmaf(eB, vB01.x, o0));
            o1 = fmaf(eA, vA01.y, fmaf(eB, vB01.y, o1));
            o2 = fmaf(eA, vA23.x, fmaf(eB, vB23.x, o2));
            o3 = fmaf(eA, vA23.y, fmaf(eB, vB23.y, o3));
        }

        const float inv = (lsum > 0.f) ? 1.f / lsum : 0.f;   // n=0: all invalid -> out=0
        *(float4*)(out + base + (size_t)n * HDIM + l * 4) =
            make_float4(o0 * inv, o1 * inv, o2 * inv, o3 * inv);
    }
}

extern "C" void kernel_launch(void* const* d_in, const int* in_sizes, int n_in,
                              void* d_out, int out_size) {
    const float* q  = (const float*)d_in[0];
    const float* k  = (const float*)d_in[1];
    const float* v  = (const float*)d_in[2];
    const float* pb = (const float*)d_in[3];
    const float* se = (const float*)d_in[4];
    (void)in_sizes; (void)n_in; (void)out_size;

    cvt_kv<<<8192, 256>>>(k, v);                              // fp32 -> interleaved fp16 mirror
    dsqg_fwd<<<NB * NH * (SEQN / 64), 256>>>(q, pb, se, (float*)d_out);
}